// round 1
// baseline (speedup 1.0000x reference)
#include <cuda_runtime.h>
#include <math.h>

#define DD 4096

// scratch (allocation-free rule: __device__ globals)
__device__ float g_xk[DD], g_xv[DD], g_xr[DD];
__device__ float g_k[DD], g_v[DD], g_r[DD], g_rv[DD];

__global__ void mix_kernel(const float* __restrict__ x,
                           const float* __restrict__ sxx,
                           const float* __restrict__ tmk,
                           const float* __restrict__ tmv,
                           const float* __restrict__ tmr) {
    int i = blockIdx.x * blockDim.x + threadIdx.x;
    if (i >= DD) return;
    float xi = x[i], si = sxx[i];
    float k = tmk[i], v = tmv[i], r = tmr[i];
    g_xk[i] = xi * k + si * (1.0f - k);
    g_xv[i] = xi * v + si * (1.0f - v);
    g_xr[i] = xi * r + si * (1.0f - r);
}

// grid: (DD rows, 3 matrices). One block per (row, matrix), 256 threads.
__global__ void matvec3_kernel(const float* __restrict__ wk,
                               const float* __restrict__ wv,
                               const float* __restrict__ wr) {
    int row = blockIdx.x;
    int m   = blockIdx.y;
    const float* W   = (m == 0) ? wk   : (m == 1) ? wv   : wr;
    const float* vec = (m == 0) ? g_xk : (m == 1) ? g_xv : g_xr;

    const float4* Wr = reinterpret_cast<const float4*>(W + (size_t)row * DD);
    const float4* Vv = reinterpret_cast<const float4*>(vec);

    float sum = 0.0f;
    #pragma unroll 4
    for (int j = threadIdx.x; j < DD / 4; j += blockDim.x) {
        float4 a = __ldg(&Wr[j]);
        float4 b = Vv[j];
        sum = fmaf(a.x, b.x, sum);
        sum = fmaf(a.y, b.y, sum);
        sum = fmaf(a.z, b.z, sum);
        sum = fmaf(a.w, b.w, sum);
    }
    #pragma unroll
    for (int o = 16; o; o >>= 1) sum += __shfl_xor_sync(0xffffffffu, sum, o);

    __shared__ float sh[8];
    int lane = threadIdx.x & 31, w = threadIdx.x >> 5;
    if (lane == 0) sh[w] = sum;
    __syncthreads();
    if (w == 0) {
        sum = (lane < (blockDim.x >> 5)) ? sh[lane] : 0.0f;
        #pragma unroll
        for (int o = 4; o; o >>= 1) sum += __shfl_xor_sync(0xffffffffu, sum, o);
        if (lane == 0) {
            if (m == 0)      g_k[row] = sum;
            else if (m == 1) g_v[row] = sum;
            else             g_r[row] = 1.0f / (1.0f + expf(-sum));
        }
    }
}

// elementwise WKV + state update. out layout: [y | x | new_aa | new_bb | new_pp]
__global__ void wkv_kernel(const float* __restrict__ x,
                           const float* __restrict__ aa,
                           const float* __restrict__ bb,
                           const float* __restrict__ pp,
                           const float* __restrict__ t_decay,
                           const float* __restrict__ t_first,
                           float* __restrict__ out) {
    int i = blockIdx.x * blockDim.x + threadIdx.x;
    if (i >= DD) return;
    float k = g_k[i], v = g_v[i], r = g_r[i];
    float ppi = pp[i], aai = aa[i], bbi = bb[i];

    float ww = t_first[i] + k;
    float p  = fmaxf(ppi, ww);
    float e1 = expf(ppi - p);
    float e2 = expf(ww - p);
    float a  = fmaf(e1, aai, e2 * v);
    float b  = fmaf(e1, bbi, e2);
    g_rv[i]  = r * (a / b);

    float ww2 = ppi + t_decay[i];
    float p2  = fmaxf(ww2, k);
    float e1b = expf(ww2 - p2);
    float e2b = expf(k - p2);

    out[DD + i]     = x[i];
    out[2 * DD + i] = fmaf(e1b, aai, e2b * v);
    out[3 * DD + i] = fmaf(e1b, bbi, e2b);
    out[4 * DD + i] = p2;
}

__global__ void matvec_out_kernel(const float* __restrict__ wo,
                                  float* __restrict__ out) {
    int row = blockIdx.x;
    const float4* Wr = reinterpret_cast<const float4*>(wo + (size_t)row * DD);
    const float4* Vv = reinterpret_cast<const float4*>(g_rv);

    float sum = 0.0f;
    #pragma unroll 4
    for (int j = threadIdx.x; j < DD / 4; j += blockDim.x) {
        float4 a = __ldg(&Wr[j]);
        float4 b = Vv[j];
        sum = fmaf(a.x, b.x, sum);
        sum = fmaf(a.y, b.y, sum);
        sum = fmaf(a.z, b.z, sum);
        sum = fmaf(a.w, b.w, sum);
    }
    #pragma unroll
    for (int o = 16; o; o >>= 1) sum += __shfl_xor_sync(0xffffffffu, sum, o);

    __shared__ float sh[8];
    int lane = threadIdx.x & 31, w = threadIdx.x >> 5;
    if (lane == 0) sh[w] = sum;
    __syncthreads();
    if (w == 0) {
        sum = (lane < (blockDim.x >> 5)) ? sh[lane] : 0.0f;
        #pragma unroll
        for (int o = 4; o; o >>= 1) sum += __shfl_xor_sync(0xffffffffu, sum, o);
        if (lane == 0) out[row] = sum;
    }
}

extern "C" void kernel_launch(void* const* d_in, const int* in_sizes, int n_in,
                              void* d_out, int out_size) {
    const float* x       = (const float*)d_in[0];
    const float* sxx     = (const float*)d_in[1];
    const float* aa      = (const float*)d_in[2];
    const float* bb      = (const float*)d_in[3];
    const float* pp      = (const float*)d_in[4];
    const float* w_key   = (const float*)d_in[5];
    const float* w_val   = (const float*)d_in[6];
    const float* w_rec   = (const float*)d_in[7];
    const float* w_out   = (const float*)d_in[8];
    const float* t_decay = (const float*)d_in[9];
    const float* t_first = (const float*)d_in[10];
    const float* t_mix_k = (const float*)d_in[11];
    const float* t_mix_v = (const float*)d_in[12];
    const float* t_mix_r = (const float*)d_in[13];
    float* out = (float*)d_out;

    mix_kernel<<<DD / 256, 256>>>(x, sxx, t_mix_k, t_mix_v, t_mix_r);
    matvec3_kernel<<<dim3(DD, 3), 256>>>(w_key, w_val, w_rec);
    wkv_kernel<<<DD / 256, 256>>>(x, aa, bb, pp, t_decay, t_first, out);
    matvec_out_kernel<<<DD, 256>>>(w_out, out);
}